// round 4
// baseline (speedup 1.0000x reference)
#include <cuda_runtime.h>

#define EPS_F 1e-5f
#define BDIM 128
#define CDIM 32
#define NA 12
#define NB 12
#define PDIM 8192

#define TPB 256
#define PTS_PER_BLOCK (TPB * 2)  // each thread handles 2 consecutive points

// Folded conv+bn weights, computed by prologue kernel each launch.
__device__ float g_wfold[CDIM * CDIM];
__device__ float g_bfold[CDIM];

// ---------------------------------------------------------------------------
// Prologue: fold bn1 + conv + bn2 into W', bias'
//   x = agg*s1 + t1 ; y = W x ; z = y*s2 + t2
//   => z[o] = sum_c (W[o][c]*s1[c]*s2[o]) * agg[c] + (s2[o]*sum_c W[o][c]*t1[c] + t2[o])
// ---------------------------------------------------------------------------
__global__ void fold_kernel(const float* __restrict__ w,
                            const float* __restrict__ g1, const float* __restrict__ b1,
                            const float* __restrict__ m1, const float* __restrict__ v1,
                            const float* __restrict__ g2, const float* __restrict__ b2,
                            const float* __restrict__ m2, const float* __restrict__ v2) {
    __shared__ float s1[CDIM], t1[CDIM], s2[CDIM], t2[CDIM];
    int t = threadIdx.x;
    if (t < CDIM) {
        float sc1 = g1[t] * rsqrtf(v1[t] + EPS_F);
        s1[t] = sc1;
        t1[t] = b1[t] - m1[t] * sc1;
        float sc2 = g2[t] * rsqrtf(v2[t] + EPS_F);
        s2[t] = sc2;
        t2[t] = b2[t] - m2[t] * sc2;
    }
    __syncthreads();
    if (t < CDIM * CDIM) {
        int o = t >> 5;
        int c = t & 31;
        g_wfold[t] = w[t] * s1[c] * s2[o];
    }
    if (t < CDIM) {
        int o = t;
        float s = 0.f;
        #pragma unroll
        for (int c = 0; c < CDIM; c++) s += w[o * CDIM + c] * t1[c];
        g_bfold[o] = s * s2[o] + t2[o];
    }
}

// ---------------------------------------------------------------------------
// Packed f32x2 helpers (sm_103a FFMA2 path — ptxas never emits this from C++)
// ---------------------------------------------------------------------------
__device__ __forceinline__ unsigned long long pack2(float lo, float hi) {
    unsigned long long r;
    asm("mov.b64 %0, {%1, %2};" : "=l"(r) : "f"(lo), "f"(hi));
    return r;
}
__device__ __forceinline__ void unpack2(unsigned long long v, float& lo, float& hi) {
    asm("mov.b64 {%0, %1}, %2;" : "=f"(lo), "=f"(hi) : "l"(v));
}
__device__ __forceinline__ unsigned long long fma2(unsigned long long a,
                                                   unsigned long long b,
                                                   unsigned long long c) {
    unsigned long long d;
    asm("fma.rn.f32x2 %0, %1, %2, %3;" : "=l"(d) : "l"(a), "l"(b), "l"(c));
    return d;
}

// ---------------------------------------------------------------------------
// Main fused kernel: gather-max + folded affine + relu.
// grid = (PDIM / PTS_PER_BLOCK, BDIM); block = TPB.
// Thread handles points (p0, p0+1) packed as f32x2 lanes.
// ---------------------------------------------------------------------------
__global__ __launch_bounds__(TPB) void feynnet_kernel(
    const float* __restrict__ feat_a, const float* __restrict__ feat_b,
    const int* __restrict__ assign_a, const int* __restrict__ assign_b,
    float* __restrict__ out) {
    __shared__ float fa[CDIM * NA];
    __shared__ float fb[CDIM * NB];
    __shared__ unsigned long long w2[CDIM * CDIM];   // (w,w) pairs, 8 KB
    __shared__ unsigned long long bias2[CDIM];

    const int t = threadIdx.x;
    const int b = blockIdx.y;

    for (int i = t; i < CDIM * NA; i += TPB) fa[i] = feat_a[b * CDIM * NA + i];
    for (int i = t; i < CDIM * NB; i += TPB) fb[i] = feat_b[b * CDIM * NB + i];
    for (int i = t; i < CDIM * CDIM; i += TPB) {
        float w = g_wfold[i];
        w2[i] = pack2(w, w);
    }
    if (t < CDIM) {
        float bb = g_bfold[t];
        bias2[t] = pack2(bb, bb);
    }
    __syncthreads();

    const int p0 = blockIdx.x * PTS_PER_BLOCK + 2 * t;

    // assign rows for points p0, p0+1 : 16B-aligned int4 loads (M=2, p0 even)
    const int4 aa = *reinterpret_cast<const int4*>(assign_a + 2 * p0);
    const int4 ab = *reinterpret_cast<const int4*>(assign_b + 2 * p0);

    // Gather + max-aggregate. Conflict-free: for fixed c the 12 candidate
    // words occupy 12 distinct banks; duplicate indices broadcast.
    unsigned long long agg[CDIM];
    #pragma unroll
    for (int c = 0; c < CDIM; c++) {
        const float* ra = fa + c * NA;
        const float* rb = fb + c * NB;
        float a0 = fmaxf(fmaxf(ra[aa.x], ra[aa.y]), fmaxf(rb[ab.x], rb[ab.y]));
        float a1 = fmaxf(fmaxf(ra[aa.z], ra[aa.w]), fmaxf(rb[ab.z], rb[ab.w]));
        agg[c] = pack2(a0, a1);
    }

    float* outp = out + (size_t)b * CDIM * PDIM + p0;

    // 4 independent accumulator chains per iteration (hide FFMA2 latency),
    // outer o-loop rolled to keep I-cache footprint small.
    #pragma unroll 1
    for (int o = 0; o < CDIM; o += 4) {
        unsigned long long acc0 = bias2[o + 0];
        unsigned long long acc1 = bias2[o + 1];
        unsigned long long acc2v = bias2[o + 2];
        unsigned long long acc3 = bias2[o + 3];
        const unsigned long long* wr = w2 + o * CDIM;
        #pragma unroll
        for (int c = 0; c < CDIM; c++) {
            unsigned long long g = agg[c];
            acc0  = fma2(wr[0 * CDIM + c], g, acc0);
            acc1  = fma2(wr[1 * CDIM + c], g, acc1);
            acc2v = fma2(wr[2 * CDIM + c], g, acc2v);
            acc3  = fma2(wr[3 * CDIM + c], g, acc3);
        }
        float x, y;
        unpack2(acc0, x, y);
        *reinterpret_cast<float2*>(outp + (size_t)(o + 0) * PDIM) =
            make_float2(fmaxf(x, 0.f), fmaxf(y, 0.f));
        unpack2(acc1, x, y);
        *reinterpret_cast<float2*>(outp + (size_t)(o + 1) * PDIM) =
            make_float2(fmaxf(x, 0.f), fmaxf(y, 0.f));
        unpack2(acc2v, x, y);
        *reinterpret_cast<float2*>(outp + (size_t)(o + 2) * PDIM) =
            make_float2(fmaxf(x, 0.f), fmaxf(y, 0.f));
        unpack2(acc3, x, y);
        *reinterpret_cast<float2*>(outp + (size_t)(o + 3) * PDIM) =
            make_float2(fmaxf(x, 0.f), fmaxf(y, 0.f));
    }
}

// ---------------------------------------------------------------------------
// Launch
// ---------------------------------------------------------------------------
extern "C" void kernel_launch(void* const* d_in, const int* in_sizes, int n_in,
                              void* d_out, int out_size) {
    const float* feat_a = (const float*)d_in[0];
    const float* feat_b = (const float*)d_in[1];
    const int* assign_a = (const int*)d_in[2];
    const int* assign_b = (const int*)d_in[3];
    const float* bn1_gamma = (const float*)d_in[4];
    const float* bn1_beta = (const float*)d_in[5];
    const float* bn1_mean = (const float*)d_in[6];
    const float* bn1_var = (const float*)d_in[7];
    const float* conv_w = (const float*)d_in[8];
    const float* bn2_gamma = (const float*)d_in[9];
    const float* bn2_beta = (const float*)d_in[10];
    const float* bn2_mean = (const float*)d_in[11];
    const float* bn2_var = (const float*)d_in[12];
    float* out = (float*)d_out;

    fold_kernel<<<1, CDIM * CDIM>>>(conv_w, bn1_gamma, bn1_beta, bn1_mean, bn1_var,
                                    bn2_gamma, bn2_beta, bn2_mean, bn2_var);

    dim3 grid(PDIM / PTS_PER_BLOCK, BDIM);
    feynnet_kernel<<<grid, TPB>>>(feat_a, feat_b, assign_a, assign_b, out);
}